// round 11
// baseline (speedup 1.0000x reference)
#include <cuda_runtime.h>
#include <cuda_fp16.h>

// Scratch (__device__ globals; zero-initialized at load). N = 100000 <= MAXN.
// All accumulators are read-then-zeroed inside the fused kernel, so every
// call starts from zeroed state (first call: static zero-init).
#define MAXN (1 << 17)
__device__ __align__(16) float  g_deg[MAXN];
__device__ __align__(16) float  g_dinv[MAXN];
__device__ __align__(16) __half g_a[MAXN];    // dinv[i]*x[i] (fp16 -> L1-friendly gathers)
__device__ __align__(16) float  g_S[MAXN];    // layer-1 aggregate (fp32 REDs)
__device__ __align__(16) __half g_u[MAXN];    // dinv[i]*t[i] (fp16)
__device__ __align__(16) float  g_acc[MAXN];  // layer-2 aggregate

// software grid-barrier counters (slots 0..4 = phase barriers, 5 = exit/reset)
__device__ unsigned g_cnt[8];

#define NB 148
#define NT 1024

// Software grid barrier. Safe: all NB blocks are co-resident (NB <= #SMs at
// >=1 block/SM), so no block waits on an unscheduled block.
__device__ __forceinline__ void gridbar(int slot, unsigned nb) {
    __syncthreads();
    if (threadIdx.x == 0) {
        __threadfence();                       // release prior global writes
        atomicAdd(&g_cnt[slot], 1u);
        while (atomicAdd(&g_cnt[slot], 0u) < nb) __nanosleep(64);
        __threadfence();                       // acquire
    }
    __syncthreads();
}

__global__ void __launch_bounds__(NT, 1)
gcn_fused(const float* __restrict__ x,
          const int* __restrict__ row, const int* __restrict__ col,
          const float* __restrict__ W1, const float* __restrict__ b1,
          const float* __restrict__ W2, const float* __restrict__ b2,
          float* __restrict__ out, int N, int E, int H, unsigned nb) {
    const int tid = blockIdx.x * NT + threadIdx.x;
    const int T   = gridDim.x * NT;
    const int E4  = E & ~3;

    // ---- P1: deg[col] += 1 (edge REDs) ----
    for (int e = tid * 4; e < E4; e += T * 4) {
        int4 c = __ldg(reinterpret_cast<const int4*>(col + e));
        atomicAdd(&g_deg[c.x], 1.0f);
        atomicAdd(&g_deg[c.y], 1.0f);
        atomicAdd(&g_deg[c.z], 1.0f);
        atomicAdd(&g_deg[c.w], 1.0f);
    }
    if (tid == 0)
        for (int e = E4; e < E; e++) atomicAdd(&g_deg[col[e]], 1.0f);
    gridbar(0, nb);

    // ---- P2: dinv = 1/sqrt(deg+1); a = dinv*x (fp16); zero deg ----
    for (int i = tid; i < N; i += T) {
        float d = g_deg[i];
        g_deg[i] = 0.0f;
        float di = 1.0f / sqrtf(d + 1.0f);     // +1 = self loop
        g_dinv[i] = di;
        g_a[i] = __float2half_rn(di * __ldg(x + i));
    }
    gridbar(1, nb);

    // ---- P3: S[col] += a[row] (gather + RED) ----
    for (int e = tid * 4; e < E4; e += T * 4) {
        int4 r = __ldg(reinterpret_cast<const int4*>(row + e));
        int4 c = __ldg(reinterpret_cast<const int4*>(col + e));
        float v0 = __half2float(__ldg(g_a + r.x));
        float v1 = __half2float(__ldg(g_a + r.y));
        float v2 = __half2float(__ldg(g_a + r.z));
        float v3 = __half2float(__ldg(g_a + r.w));
        atomicAdd(&g_S[c.x], v0);
        atomicAdd(&g_S[c.y], v1);
        atomicAdd(&g_S[c.z], v2);
        atomicAdd(&g_S[c.w], v3);
    }
    if (tid == 0)
        for (int e = E4; e < E; e++)
            atomicAdd(&g_S[col[e]], __half2float(g_a[row[e]]));
    gridbar(2, nb);

    // ---- P4: s = dinv*(S + a); t = MLP(s); u = dinv*t; zero S ----
    for (int i = tid; i < N; i += T) {
        float di = g_dinv[i];
        float Sv = g_S[i];
        g_S[i] = 0.0f;
        float s = di * (Sv + __half2float(g_a[i]));
        float acc = 0.0f;
        #pragma unroll 16
        for (int k = 0; k < H; k++) {
            float h = fmaf(__ldg(&W1[k]), s, __ldg(&b1[k]));
            h = fmaxf(h, 0.0f);
            acc = fmaf(h, __ldg(&W2[k]), acc);
        }
        g_u[i] = __float2half_rn(di * acc);
    }
    gridbar(3, nb);

    // ---- P5: acc[col] += u[row] ----
    for (int e = tid * 4; e < E4; e += T * 4) {
        int4 r = __ldg(reinterpret_cast<const int4*>(row + e));
        int4 c = __ldg(reinterpret_cast<const int4*>(col + e));
        float v0 = __half2float(__ldg(g_u + r.x));
        float v1 = __half2float(__ldg(g_u + r.y));
        float v2 = __half2float(__ldg(g_u + r.z));
        float v3 = __half2float(__ldg(g_u + r.w));
        atomicAdd(&g_acc[c.x], v0);
        atomicAdd(&g_acc[c.y], v1);
        atomicAdd(&g_acc[c.z], v2);
        atomicAdd(&g_acc[c.w], v3);
    }
    if (tid == 0)
        for (int e = E4; e < E; e++)
            atomicAdd(&g_acc[col[e]], __half2float(g_u[row[e]]));
    gridbar(4, nb);

    // ---- P6: out = dinv*(acc + u) + b2; zero acc ----
    float bb = __ldg(b2);
    for (int i = tid; i < N; i += T) {
        float av = g_acc[i];
        g_acc[i] = 0.0f;
        out[i] = g_dinv[i] * (av + __half2float(g_u[i])) + bb;
    }

    // ---- exit: last block to arrive resets all barrier counters ----
    __syncthreads();
    if (threadIdx.x == 0) {
        __threadfence();
        unsigned prev = atomicAdd(&g_cnt[5], 1u);
        if (prev + 1 == nb) {
            // everyone has passed every barrier; safe to reset for next call
            #pragma unroll
            for (int s = 0; s < 6; s++) g_cnt[s] = 0;
            __threadfence();
        }
    }
}

// ---------------------------------------------------------------------------
// Launch
// ---------------------------------------------------------------------------

extern "C" void kernel_launch(void* const* d_in, const int* in_sizes, int n_in,
                              void* d_out, int out_size) {
    const float* x    = (const float*)d_in[0];
    const int*   eidx = (const int*)d_in[1];    // [2, E] int32
    const float* W1   = (const float*)d_in[2];
    const float* b1   = (const float*)d_in[3];
    const float* W2   = (const float*)d_in[4];
    const float* b2   = (const float*)d_in[5];
    float*       out  = (float*)d_out;

    int N = in_sizes[0];
    int E = in_sizes[1] / 2;
    int H = in_sizes[3];

    const int* row = eidx;
    const int* col = eidx + E;

    gcn_fused<<<NB, NT>>>(x, row, col, W1, b1, W2, b2, out, N, E, H, (unsigned)NB);
}